// round 1
// baseline (speedup 1.0000x reference)
#include <cuda_runtime.h>
#include <math.h>

#define SEQ    2048
#define BATCH  2
#define DM     512
#define QKVN   1024
#define VDIM   8192
#define NSPLIT 32   // split-K for Wv@Wo
#define BSPLIT 64   // split-K for bv@Wo

// ---------------- scratch (static device globals; no allocation) ----------------
__device__ float g_QKV[BATCH * SEQ * QKVN];        // 16.8 MB
__device__ float g_WvWoP[NSPLIT * DM * DM];        // 33.6 MB
__device__ float g_WvWo[DM * DM];                  // 1 MB
__device__ float g_bvWoP[BSPLIT * DM];
__device__ float g_bvWo[DM];
__device__ float g_VW[BATCH * SEQ * DM];           // 8.4 MB
__device__ float g_L1[BATCH * SEQ * SEQ];          // 33.6 MB (reused as diff_attn)
__device__ float g_L2[BATCH * SEQ * SEQ];          // 33.6 MB
__device__ float g_lam;

// ---------------- generic fp32 tiled GEMM ----------------
// C[M,N] = alpha * A @ B (+ bias[col]), row-major.
// TRANSB=false: B is [K,N]. TRANSB=true: B is [N,K] (computes A @ B^T).
// blockIdx.z advances A/B/C by sA/sB/sC elements (batching or split-K).
// Requires M%128==0, N%128==0, K%8==0.
template <bool TRANSB>
__global__ __launch_bounds__(256)
void sgemm_kernel(const float* __restrict__ A, const float* __restrict__ B,
                  const float* __restrict__ bias, float* __restrict__ C,
                  int M, int N, int K, int lda, int ldb, int ldc,
                  long long sA, long long sB, long long sC, float alpha)
{
    constexpr int BM = 128, BN = 128, BK = 8, TM = 8, TN = 8;
    __shared__ float As[BK][BM];
    __shared__ float Bs[BK][BN];

    A += (long long)blockIdx.z * sA;
    B += (long long)blockIdx.z * sB;
    C += (long long)blockIdx.z * sC;

    const int tid = threadIdx.x;          // 0..255
    const int block_row = blockIdx.y * BM;
    const int block_col = blockIdx.x * BN;

    const int ty = tid / 16;              // 0..15
    const int tx = tid % 16;              // 0..15

    // A tile load: 128 rows x 8 cols, one float4 per thread
    const int a_row = tid >> 1;           // 0..127
    const int a_col = (tid & 1) * 4;      // 0 or 4
    // B tile load (NN): 8 rows x 128 cols
    const int b_row = tid >> 5;           // 0..7
    const int b_col = (tid & 31) * 4;     // 0..124
    // B tile load (NT): B is [N,K]; need Bs[k][n]
    const int bt_n = tid >> 1;            // 0..127
    const int bt_k = (tid & 1) * 4;       // 0 or 4

    float acc[TM][TN] = {};

    for (int k0 = 0; k0 < K; k0 += BK) {
        float4 av = *(const float4*)&A[(long long)(block_row + a_row) * lda + k0 + a_col];
        As[a_col + 0][a_row] = av.x;
        As[a_col + 1][a_row] = av.y;
        As[a_col + 2][a_row] = av.z;
        As[a_col + 3][a_row] = av.w;
        if (TRANSB) {
            float4 bvv = *(const float4*)&B[(long long)(block_col + bt_n) * ldb + k0 + bt_k];
            Bs[bt_k + 0][bt_n] = bvv.x;
            Bs[bt_k + 1][bt_n] = bvv.y;
            Bs[bt_k + 2][bt_n] = bvv.z;
            Bs[bt_k + 3][bt_n] = bvv.w;
        } else {
            float4 bvv = *(const float4*)&B[(long long)(k0 + b_row) * ldb + block_col + b_col];
            *(float4*)&Bs[b_row][b_col] = bvv;
        }
        __syncthreads();

        #pragma unroll
        for (int k = 0; k < BK; k++) {
            float4 a0 = *(const float4*)&As[k][ty * TM];
            float4 a1 = *(const float4*)&As[k][ty * TM + 4];
            float4 b0 = *(const float4*)&Bs[k][tx * TN];
            float4 b1 = *(const float4*)&Bs[k][tx * TN + 4];
            float af[TM] = {a0.x, a0.y, a0.z, a0.w, a1.x, a1.y, a1.z, a1.w};
            float bf[TN] = {b0.x, b0.y, b0.z, b0.w, b1.x, b1.y, b1.z, b1.w};
            #pragma unroll
            for (int i = 0; i < TM; i++)
                #pragma unroll
                for (int j = 0; j < TN; j++)
                    acc[i][j] += af[i] * bf[j];
        }
        __syncthreads();
    }

    #pragma unroll
    for (int i = 0; i < TM; i++) {
        const long long row = block_row + ty * TM + i;
        #pragma unroll
        for (int j = 0; j < TN; j += 4) {
            const int col = block_col + tx * TN + j;
            float4 v;
            v.x = acc[i][j + 0] * alpha;
            v.y = acc[i][j + 1] * alpha;
            v.z = acc[i][j + 2] * alpha;
            v.w = acc[i][j + 3] * alpha;
            if (bias) {
                v.x += bias[col + 0];
                v.y += bias[col + 1];
                v.z += bias[col + 2];
                v.w += bias[col + 3];
            }
            *(float4*)&C[row * ldc + col] = v;
        }
    }
}

// ---------------- split-K reductions (deterministic, no atomics) ----------------
__global__ void reduce_wvwo_kernel()
{
    int i = blockIdx.x * blockDim.x + threadIdx.x;
    if (i < DM * DM) {
        float s = 0.f;
        #pragma unroll
        for (int z = 0; z < NSPLIT; z++) s += g_WvWoP[z * DM * DM + i];
        g_WvWo[i] = s;
    }
}

__global__ void bvwo_part_kernel(const float* __restrict__ bv, const float* __restrict__ Wo)
{
    int n = threadIdx.x;                  // 512
    int z = blockIdx.x;                   // 64 chunks of 128
    float s = 0.f;
    int k0 = z * (VDIM / BSPLIT);
    for (int k = k0; k < k0 + VDIM / BSPLIT; k++)
        s += bv[k] * Wo[(long long)k * DM + n];
    g_bvWoP[z * DM + n] = s;
}

__global__ void reduce_bvwo_kernel()
{
    int n = threadIdx.x;
    float s = 0.f;
    #pragma unroll
    for (int z = 0; z < BSPLIT; z++) s += g_bvWoP[z * DM + n];
    g_bvWo[n] = s;
}

// ---------------- lambda scalar ----------------
__global__ void lam_kernel(const float* __restrict__ lq1, const float* __restrict__ lk1,
                           const float* __restrict__ lq2, const float* __restrict__ lk2)
{
    __shared__ float s1[64], s2[64];
    int t = threadIdx.x;
    s1[t] = lq1[t] * lk1[t];
    s2[t] = lq2[t] * lk2[t];
    __syncthreads();
    if (t == 0) {
        float a = 0.f, b = 0.f;
        for (int i = 0; i < 64; i++) { a += s1[i]; b += s2[i]; }
        // LAYER_INDEX = 0
        g_lam = expf(a) - expf(b) + (0.8f - 0.6f * expf(-0.3f * 0.0f));
    }
}

// ---------------- fused dual softmax + differential combine ----------------
// One block per attention row. diff = softmax(L1) - lam * softmax(L2), in-place into L1.
__global__ __launch_bounds__(256)
void softmax_diff_kernel(float* __restrict__ L1, const float* __restrict__ L2)
{
    __shared__ float red[16];
    const long long base = (long long)blockIdx.x * SEQ;
    const int t = threadIdx.x;

    float v1[8], v2[8];
    #pragma unroll
    for (int i = 0; i < 8; i++) {
        v1[i] = L1[base + t + i * 256];
        v2[i] = L2[base + t + i * 256];
    }

    float m1 = -1e30f, m2 = -1e30f;
    #pragma unroll
    for (int i = 0; i < 8; i++) { m1 = fmaxf(m1, v1[i]); m2 = fmaxf(m2, v2[i]); }
    #pragma unroll
    for (int o = 16; o > 0; o >>= 1) {
        m1 = fmaxf(m1, __shfl_xor_sync(0xffffffffu, m1, o));
        m2 = fmaxf(m2, __shfl_xor_sync(0xffffffffu, m2, o));
    }
    const int w = t >> 5, l = t & 31;
    if (l == 0) { red[w] = m1; red[8 + w] = m2; }
    __syncthreads();
    float M1 = red[0], M2 = red[8];
    #pragma unroll
    for (int i = 1; i < 8; i++) { M1 = fmaxf(M1, red[i]); M2 = fmaxf(M2, red[8 + i]); }
    __syncthreads();

    float sum1 = 0.f, sum2 = 0.f;
    #pragma unroll
    for (int i = 0; i < 8; i++) {
        v1[i] = __expf(v1[i] - M1); sum1 += v1[i];
        v2[i] = __expf(v2[i] - M2); sum2 += v2[i];
    }
    #pragma unroll
    for (int o = 16; o > 0; o >>= 1) {
        sum1 += __shfl_xor_sync(0xffffffffu, sum1, o);
        sum2 += __shfl_xor_sync(0xffffffffu, sum2, o);
    }
    if (l == 0) { red[w] = sum1; red[8 + w] = sum2; }
    __syncthreads();
    float S1 = 0.f, S2 = 0.f;
    #pragma unroll
    for (int i = 0; i < 8; i++) { S1 += red[i]; S2 += red[8 + i]; }

    const float r1 = 1.f / S1;
    const float r2 = g_lam / S2;
    #pragma unroll
    for (int i = 0; i < 8; i++)
        L1[base + t + i * 256] = v1[i] * r1 - v2[i] * r2;
}

// ---------------- driver ----------------
extern "C" void kernel_launch(void* const* d_in, const int* in_sizes, int n_in,
                              void* d_out, int out_size)
{
    const float* x    = (const float*)d_in[0];
    const float* Wqkv = (const float*)d_in[1];
    const float* bqkv = (const float*)d_in[2];
    const float* Wv   = (const float*)d_in[3];
    const float* bv   = (const float*)d_in[4];
    const float* Wo   = (const float*)d_in[5];
    const float* bo   = (const float*)d_in[6];
    const float* lq1  = (const float*)d_in[7];
    const float* lk1  = (const float*)d_in[8];
    const float* lq2  = (const float*)d_in[9];
    const float* lk2  = (const float*)d_in[10];
    float* out = (float*)d_out;

    float *QKV, *WvWoP, *WvWo, *VW, *L1, *L2, *bvWo;
    cudaGetSymbolAddress((void**)&QKV,   g_QKV);
    cudaGetSymbolAddress((void**)&WvWoP, g_WvWoP);
    cudaGetSymbolAddress((void**)&WvWo,  g_WvWo);
    cudaGetSymbolAddress((void**)&VW,    g_VW);
    cudaGetSymbolAddress((void**)&L1,    g_L1);
    cudaGetSymbolAddress((void**)&L2,    g_L2);
    cudaGetSymbolAddress((void**)&bvWo,  g_bvWo);

    const int MROWS = BATCH * SEQ;      // 4096
    const float scale = 0.125f;         // 1/sqrt(64)

    // 1) Wv@Wo split-K partials: per z, [512,512] += Wv[:, z*256:(z+1)*256] @ Wo[z*256:(z+1)*256, :]
    {
        dim3 g(DM / 128, DM / 128, NSPLIT);
        sgemm_kernel<false><<<g, 256>>>(Wv, Wo, nullptr, WvWoP,
                                        DM, DM, VDIM / NSPLIT, VDIM, DM, DM,
                                        (long long)(VDIM / NSPLIT),
                                        (long long)(VDIM / NSPLIT) * DM,
                                        (long long)DM * DM, 1.0f);
    }
    reduce_wvwo_kernel<<<(DM * DM + 255) / 256, 256>>>();
    bvwo_part_kernel<<<BSPLIT, DM>>>(bv, Wo);
    reduce_bvwo_kernel<<<1, DM>>>();

    // 2) QKV = x @ Wqkv + bqkv   [4096,1024], K=512
    {
        dim3 g(QKVN / 128, MROWS / 128, 1);
        sgemm_kernel<false><<<g, 256>>>(x, Wqkv, bqkv, QKV,
                                        MROWS, QKVN, DM, DM, QKVN, QKVN,
                                        0, 0, 0, 1.0f);
    }
    // 3) VW = x @ WvWo + bvWo   [4096,512], K=512
    {
        dim3 g(DM / 128, MROWS / 128, 1);
        sgemm_kernel<false><<<g, 256>>>(x, WvWo, bvWo, VW,
                                        MROWS, DM, DM, DM, DM, DM,
                                        0, 0, 0, 1.0f);
    }
    // 4) lambda
    lam_kernel<<<1, 64>>>(lq1, lk1, lq2, lk2);

    // 5) logits: L1 = Q1 @ K1^T * scale, L2 = Q2 @ K2^T * scale (batched over z)
    {
        dim3 g(SEQ / 128, SEQ / 128, BATCH);
        const long long sQ = (long long)SEQ * QKVN;
        const long long sL = (long long)SEQ * SEQ;
        sgemm_kernel<true><<<g, 256>>>(QKV + 0,   QKV + 512, nullptr, L1,
                                       SEQ, SEQ, DM / 2, QKVN, QKVN, SEQ,
                                       sQ, sQ, sL, scale);
        sgemm_kernel<true><<<g, 256>>>(QKV + 256, QKV + 768, nullptr, L2,
                                       SEQ, SEQ, DM / 2, QKVN, QKVN, SEQ,
                                       sQ, sQ, sL, scale);
    }

    // 6) diff_attn = softmax(L1) - lam * softmax(L2), in-place into L1
    softmax_diff_kernel<<<BATCH * SEQ, 256>>>(L1, L2);

    // 7) out = diff_attn @ VW + bo   per batch: [2048,512], K=2048
    {
        dim3 g(DM / 128, SEQ / 128, BATCH);
        sgemm_kernel<false><<<g, 256>>>(L1, VW, bo, out,
                                        SEQ, DM, SEQ, SEQ, DM, DM,
                                        (long long)SEQ * SEQ,
                                        (long long)SEQ * DM,
                                        (long long)SEQ * DM, 1.0f);
    }
}

// round 4
// speedup vs baseline: 2.5904x; 2.5904x over previous
#include <cuda_runtime.h>
#include <cuda_bf16.h>
#include <stdint.h>
#include <math.h>

#define SEQ    2048
#define BATCH  2
#define DM     512
#define QKVN   1024
#define VDIM   8192
#define MR     (BATCH*SEQ)    // 4096
#define WSPLIT 8              // split-K for Wv@Wo
#define BSPLIT 64             // split-K for bv@Wo

// ---------------- scratch (static device globals; no allocation) ----------------
__device__ __nv_bfloat16 g_xh[MR*DM],        g_xl[MR*DM];
__device__ __nv_bfloat16 g_Wvh[DM*VDIM],     g_Wvl[DM*VDIM];
__device__ __nv_bfloat16 g_WoTh[DM*VDIM],    g_WoTl[DM*VDIM];
__device__ __nv_bfloat16 g_WqkvTh[QKVN*DM],  g_WqkvTl[QKVN*DM];
__device__ __nv_bfloat16 g_WvWoTh[DM*DM],    g_WvWoTl[DM*DM];
__device__ __nv_bfloat16 g_QKVh[MR*QKVN],    g_QKVl[MR*QKVN];
__device__ __nv_bfloat16 g_VWTh[BATCH*DM*SEQ], g_VWTl[BATCH*DM*SEQ];
__device__ __nv_bfloat16 g_Dh[(size_t)BATCH*SEQ*SEQ], g_Dl[(size_t)BATCH*SEQ*SEQ];
__device__ float g_QKV[MR*QKVN];
__device__ float g_WvWoP[WSPLIT*DM*DM];
__device__ float g_WvWo[DM*DM];
__device__ float g_bvWoP[BSPLIT*DM];
__device__ float g_bvWo[DM];
__device__ float g_VW[MR*DM];
__device__ float g_L1[(size_t)BATCH*SEQ*SEQ];
__device__ float g_L2[(size_t)BATCH*SEQ*SEQ];
__device__ float g_lam;

// ---------------- PTX helpers (sm_100-safe: HMMA/LDSM/LDGSTS only) ----------------
__device__ __forceinline__ uint32_t s2u(const void* p) {
    uint32_t a;
    asm("{ .reg .u64 t; cvta.to.shared.u64 t, %1; cvt.u32.u64 %0, t; }" : "=r"(a) : "l"(p));
    return a;
}

#define CP16(dst, src) \
    asm volatile("cp.async.cg.shared.global [%0], [%1], 16;" :: "r"(dst), "l"(src))

__device__ __forceinline__ void ldm_x4(uint32_t* r, uint32_t addr) {
    asm volatile("ldmatrix.sync.aligned.m8n8.x4.shared.b16 {%0, %1, %2, %3}, [%4];"
                 : "=r"(r[0]), "=r"(r[1]), "=r"(r[2]), "=r"(r[3]) : "r"(addr));
}

__device__ __forceinline__ void mma16816(float* c, const uint32_t* a, const uint32_t* b) {
    asm volatile(
        "mma.sync.aligned.m16n8k16.row.col.f32.bf16.bf16.f32 "
        "{%0, %1, %2, %3}, {%4, %5, %6, %7}, {%8, %9}, {%0, %1, %2, %3};"
        : "+f"(c[0]), "+f"(c[1]), "+f"(c[2]), "+f"(c[3])
        : "r"(a[0]), "r"(a[1]), "r"(a[2]), "r"(a[3]), "r"(b[0]), "r"(b[1]));
}

// ---------------- HMMA NT GEMM (bf16 hi/lo split, fp32 accum) ----------------
// C[M,N] = alpha * A @ B^T (+ bias[col]).  A: [M,K] lda, B: [N,K] ldb, K-contiguous.
// 128x128 tile, BK=64, 2-stage cp.async double buffer, 8 warps (4m x 2n), warp 32x64.
// blockIdx.z advances by zA/zB/zC elements. Requires M%128==0, N%128==0, K%64==0.
#define TSTRIDE     144                 // smem row stride bytes (128 data + 16 pad)
#define MAT_BYTES   (128 * TSTRIDE)     // 18432
#define STAGE_BYTES (4 * MAT_BYTES)     // 73728 (Ah, Al, Bh, Bl)
#define SMEM_DYN    (2 * STAGE_BYTES)   // 147456

__global__ __launch_bounds__(256)
void tgemm_nt(const __nv_bfloat16* __restrict__ Ah, const __nv_bfloat16* __restrict__ Al,
              const __nv_bfloat16* __restrict__ Bh, const __nv_bfloat16* __restrict__ Bl,
              const float* __restrict__ bias, float* __restrict__ C,
              int K, int lda, int ldb, int ldc,
              long long zA, long long zB, long long zC, float alpha)
{
    extern __shared__ char dsm[];
    const uint32_t sbase = s2u(dsm);
    const int tid = threadIdx.x;
    const int lane = tid & 31;
    const int wid = tid >> 5;
    const long long z = blockIdx.z;
    Ah += z * zA;  Al += z * zA;
    Bh += z * zB;  Bl += z * zB;
    C  += z * zC;
    const int brow = blockIdx.y * 128;
    const int bcol = blockIdx.x * 128;
    const int wm0 = (wid & 3) * 32;      // warp m offset within tile
    const int wn0 = (wid >> 2) * 64;     // warp n offset within tile

    float acc[2][8][4];
    #pragma unroll
    for (int i = 0; i < 2; i++)
        #pragma unroll
        for (int j = 0; j < 8; j++)
            #pragma unroll
            for (int k = 0; k < 4; k++) acc[i][j][k] = 0.f;

    auto load_stage = [&](int s, int c) {
        const uint32_t sb = sbase + s * STAGE_BYTES;
        #pragma unroll
        for (int j = 0; j < 4; j++) {
            const int v = tid + j * 256;         // 0..1023
            const int row = v >> 3;              // 0..127
            const int c16 = v & 7;               // 16B block within 128B row
            const long long ga = (long long)(brow + row) * lda + c * 64 + c16 * 8;
            const long long gb = (long long)(bcol + row) * ldb + c * 64 + c16 * 8;
            const uint32_t so = row * TSTRIDE + c16 * 16;
            CP16(sb + so,                 Ah + ga);
            CP16(sb + MAT_BYTES + so,     Al + ga);
            CP16(sb + 2 * MAT_BYTES + so, Bh + gb);
            CP16(sb + 3 * MAT_BYTES + so, Bl + gb);
        }
    };

    auto compute_stage = [&](int s) {
        const uint32_t sb = sbase + s * STAGE_BYTES;
        const uint32_t aH = sb, aL = sb + MAT_BYTES;
        const uint32_t bH = sb + 2 * MAT_BYTES, bL = sb + 3 * MAT_BYTES;
        #pragma unroll
        for (int ks = 0; ks < 64; ks += 16) {
            uint32_t ah[2][4], al[2][4], bh[8][2], bl[8][2];
            #pragma unroll
            for (int mt = 0; mt < 2; mt++) {
                const int r  = wm0 + mt * 16 + (lane & 15);
                const int kk = ks + ((lane >> 4) & 1) * 8;
                const uint32_t off = r * TSTRIDE + kk * 2;
                ldm_x4(ah[mt], aH + off);
                ldm_x4(al[mt], aL + off);
            }
            #pragma unroll
            for (int nt = 0; nt < 4; nt++) {
                const int r  = wn0 + nt * 16 + (lane & 7) + ((lane >> 4) & 1) * 8;
                const int kk = ks + ((lane >> 3) & 1) * 8;
                const uint32_t off = r * TSTRIDE + kk * 2;
                uint32_t t0[4], t1[4];
                ldm_x4(t0, bH + off);
                ldm_x4(t1, bL + off);
                bh[2*nt][0] = t0[0]; bh[2*nt][1] = t0[1];
                bh[2*nt+1][0] = t0[2]; bh[2*nt+1][1] = t0[3];
                bl[2*nt][0] = t1[0]; bl[2*nt][1] = t1[1];
                bl[2*nt+1][0] = t1[2]; bl[2*nt+1][1] = t1[3];
            }
            // term 1: hi*hi
            #pragma unroll
            for (int mt = 0; mt < 2; mt++)
                #pragma unroll
                for (int n8 = 0; n8 < 8; n8++)
                    mma16816(acc[mt][n8], ah[mt], bh[n8]);
            // term 2: hi*lo
            #pragma unroll
            for (int mt = 0; mt < 2; mt++)
                #pragma unroll
                for (int n8 = 0; n8 < 8; n8++)
                    mma16816(acc[mt][n8], ah[mt], bl[n8]);
            // term 3: lo*hi
            #pragma unroll
            for (int mt = 0; mt < 2; mt++)
                #pragma unroll
                for (int n8 = 0; n8 < 8; n8++)
                    mma16816(acc[mt][n8], al[mt], bh[n8]);
        }
    };

    const int NC = K >> 6;

    load_stage(0, 0);
    asm volatile("cp.async.commit_group;" ::: "memory");

    for (int c = 0; c < NC; c++) {
        if (c + 1 < NC) {
            load_stage((c + 1) & 1, c + 1);
            asm volatile("cp.async.commit_group;" ::: "memory");
            asm volatile("cp.async.wait_group 1;" ::: "memory");
        } else {
            asm volatile("cp.async.wait_group 0;" ::: "memory");
        }
        __syncthreads();
        compute_stage(c & 1);
        __syncthreads();
    }

    // epilogue: mma C layout -> global
    #pragma unroll
    for (int mt = 0; mt < 2; mt++) {
        const int row0 = brow + wm0 + mt * 16 + (lane >> 2);
        #pragma unroll
        for (int n8 = 0; n8 < 8; n8++) {
            const int col = bcol + wn0 + n8 * 8 + (lane & 3) * 2;
            float b0 = 0.f, b1 = 0.f;
            if (bias) { b0 = bias[col]; b1 = bias[col + 1]; }
            float2 v0, v1;
            v0.x = acc[mt][n8][0] * alpha + b0;
            v0.y = acc[mt][n8][1] * alpha + b1;
            v1.x = acc[mt][n8][2] * alpha + b0;
            v1.y = acc[mt][n8][3] * alpha + b1;
            *(float2*)&C[(long long)row0 * ldc + col] = v0;
            *(float2*)&C[(long long)(row0 + 8) * ldc + col] = v1;
        }
    }
}

// ---------------- fp32 -> bf16 hi/lo converters ----------------
__global__ void conv_hl(const float* __restrict__ in, __nv_bfloat16* __restrict__ oh,
                        __nv_bfloat16* __restrict__ ol, long long n)
{
    long long i = (long long)blockIdx.x * blockDim.x + threadIdx.x;
    if (i < n) {
        float a = in[i];
        __nv_bfloat16 h = __float2bfloat16(a);
        oh[i] = h;
        ol[i] = __float2bfloat16(a - __bfloat162float(h));
    }
}

// in: fp32 [Z, R, C] -> out hi/lo: [Z, C, R]
__global__ void convT_hl(const float* __restrict__ in, __nv_bfloat16* __restrict__ oh,
                         __nv_bfloat16* __restrict__ ol, int R, int C)
{
    __shared__ float t[32][33];
    const long long zo = (long long)blockIdx.z * R * C;
    const int r0 = blockIdx.y * 32, c0 = blockIdx.x * 32;
    const int tx = threadIdx.x, ty = threadIdx.y;
    #pragma unroll
    for (int i = 0; i < 32; i += 8)
        t[ty + i][tx] = in[zo + (long long)(r0 + ty + i) * C + (c0 + tx)];
    __syncthreads();
    #pragma unroll
    for (int i = 0; i < 32; i += 8) {
        float a = t[tx][ty + i];
        __nv_bfloat16 h = __float2bfloat16(a);
        long long oi = zo + (long long)(c0 + ty + i) * R + (r0 + tx);
        oh[oi] = h;
        ol[oi] = __float2bfloat16(a - __bfloat162float(h));
    }
}

// ---------------- split-K reductions (deterministic) ----------------
__global__ void reduce_wvwo_kernel()
{
    int i = blockIdx.x * blockDim.x + threadIdx.x;
    if (i < DM * DM) {
        float s = 0.f;
        #pragma unroll
        for (int zz = 0; zz < WSPLIT; zz++) s += g_WvWoP[zz * DM * DM + i];
        g_WvWo[i] = s;
    }
}

__global__ void bvwo_part_kernel(const float* __restrict__ bv, const float* __restrict__ Wo)
{
    int n = threadIdx.x;
    int zz = blockIdx.x;
    float s = 0.f;
    int k0 = zz * (VDIM / BSPLIT);
    for (int k = k0; k < k0 + VDIM / BSPLIT; k++)
        s += bv[k] * Wo[(long long)k * DM + n];
    g_bvWoP[zz * DM + n] = s;
}

__global__ void reduce_bvwo_kernel()
{
    int n = threadIdx.x;
    float s = 0.f;
    #pragma unroll
    for (int zz = 0; zz < BSPLIT; zz++) s += g_bvWoP[zz * DM + n];
    g_bvWo[n] = s;
}

// ---------------- lambda scalar ----------------
__global__ void lam_kernel(const float* __restrict__ lq1, const float* __restrict__ lk1,
                           const float* __restrict__ lq2, const float* __restrict__ lk2)
{
    __shared__ float s1[64], s2[64];
    int t = threadIdx.x;
    s1[t] = lq1[t] * lk1[t];
    s2[t] = lq2[t] * lk2[t];
    __syncthreads();
    if (t == 0) {
        float a = 0.f, b = 0.f;
        for (int i = 0; i < 64; i++) { a += s1[i]; b += s2[i]; }
        g_lam = expf(a) - expf(b) + (0.8f - 0.6f * expf(-0.3f * 0.0f));
    }
}

// ---------------- fused dual softmax + diff; emits bf16 hi/lo ----------------
__global__ __launch_bounds__(256)
void softmax_diff_kernel(const float* __restrict__ L1, const float* __restrict__ L2)
{
    __shared__ float red[16];
    const long long bbase = (long long)blockIdx.x * SEQ;
    const int t = threadIdx.x;

    float v1[8], v2[8];
    #pragma unroll
    for (int i = 0; i < 8; i++) {
        v1[i] = L1[bbase + t + i * 256];
        v2[i] = L2[bbase + t + i * 256];
    }

    float m1 = -1e30f, m2 = -1e30f;
    #pragma unroll
    for (int i = 0; i < 8; i++) { m1 = fmaxf(m1, v1[i]); m2 = fmaxf(m2, v2[i]); }
    #pragma unroll
    for (int o = 16; o > 0; o >>= 1) {
        m1 = fmaxf(m1, __shfl_xor_sync(0xffffffffu, m1, o));
        m2 = fmaxf(m2, __shfl_xor_sync(0xffffffffu, m2, o));
    }
    const int w = t >> 5, l = t & 31;
    if (l == 0) { red[w] = m1; red[8 + w] = m2; }
    __syncthreads();
    float M1 = red[0], M2 = red[8];
    #pragma unroll
    for (int i = 1; i < 8; i++) { M1 = fmaxf(M1, red[i]); M2 = fmaxf(M2, red[8 + i]); }
    __syncthreads();

    float s1 = 0.f, s2 = 0.f;
    #pragma unroll
    for (int i = 0; i < 8; i++) {
        v1[i] = __expf(v1[i] - M1); s1 += v1[i];
        v2[i] = __expf(v2[i] - M2); s2 += v2[i];
    }
    #pragma unroll
    for (int o = 16; o > 0; o >>= 1) {
        s1 += __shfl_xor_sync(0xffffffffu, s1, o);
        s2 += __shfl_xor_sync(0xffffffffu, s2, o);
    }
    if (l == 0) { red[w] = s1; red[8 + w] = s2; }
    __syncthreads();
    float S1 = 0.f, S2 = 0.f;
    #pragma unroll
    for (int i = 0; i < 8; i++) { S1 += red[i]; S2 += red[8 + i]; }

    const float r1 = 1.f / S1;
    const float r2 = g_lam / S2;
    #pragma unroll
    for (int i = 0; i < 8; i++) {
        float d = v1[i] * r1 - v2[i] * r2;
        __nv_bfloat16 h = __float2bfloat16(d);
        long long idx = bbase + t + i * 256;
        g_Dh[idx] = h;
        g_Dl[idx] = __float2bfloat16(d - __bfloat162float(h));
    }
}

// ---------------- driver ----------------
extern "C" void kernel_launch(void* const* d_in, const int* in_sizes, int n_in,
                              void* d_out, int out_size)
{
    const float* x    = (const float*)d_in[0];
    const float* Wqkv = (const float*)d_in[1];
    const float* bqkv = (const float*)d_in[2];
    const float* Wv   = (const float*)d_in[3];
    const float* bv   = (const float*)d_in[4];
    const float* Wo   = (const float*)d_in[5];
    const float* bo   = (const float*)d_in[6];
    const float* lq1  = (const float*)d_in[7];
    const float* lk1  = (const float*)d_in[8];
    const float* lq2  = (const float*)d_in[9];
    const float* lk2  = (const float*)d_in[10];
    float* out = (float*)d_out;

    cudaFuncSetAttribute(tgemm_nt, cudaFuncAttributeMaxDynamicSharedMemorySize, SMEM_DYN);

    __nv_bfloat16 *xh, *xl, *Wvh, *Wvl, *WoTh, *WoTl, *WqkvTh, *WqkvTl;
    __nv_bfloat16 *WvWoTh, *WvWoTl, *QKVh, *QKVl, *VWTh, *VWTl, *Dh, *Dl;
    float *QKV, *WvWoP, *WvWo, *bvWo, *VW, *L1, *L2;
    cudaGetSymbolAddress((void**)&xh, g_xh);       cudaGetSymbolAddress((void**)&xl, g_xl);
    cudaGetSymbolAddress((void**)&Wvh, g_Wvh);     cudaGetSymbolAddress((void**)&Wvl, g_Wvl);
    cudaGetSymbolAddress((void**)&WoTh, g_WoTh);   cudaGetSymbolAddress((void**)&WoTl, g_WoTl);
    cudaGetSymbolAddress((void**)&WqkvTh, g_WqkvTh); cudaGetSymbolAddress((void**)&WqkvTl, g_WqkvTl);
    cudaGetSymbolAddress((void**)&WvWoTh, g_WvWoTh); cudaGetSymbolAddress((void**)&WvWoTl, g_WvWoTl);
    cudaGetSymbolAddress((void**)&QKVh, g_QKVh);   cudaGetSymbolAddress((void**)&QKVl, g_QKVl);
    cudaGetSymbolAddress((void**)&VWTh, g_VWTh);   cudaGetSymbolAddress((void**)&VWTl, g_VWTl);
    cudaGetSymbolAddress((void**)&Dh, g_Dh);       cudaGetSymbolAddress((void**)&Dl, g_Dl);
    cudaGetSymbolAddress((void**)&QKV, g_QKV);
    cudaGetSymbolAddress((void**)&WvWoP, g_WvWoP);
    cudaGetSymbolAddress((void**)&WvWo, g_WvWo);
    cudaGetSymbolAddress((void**)&bvWo, g_bvWo);
    cudaGetSymbolAddress((void**)&VW, g_VW);
    cudaGetSymbolAddress((void**)&L1, g_L1);
    cudaGetSymbolAddress((void**)&L2, g_L2);

    const long long sQ = (long long)SEQ * QKVN;
    const long long sL = (long long)SEQ * SEQ;
    const dim3 tB(32, 8);

    // ---- input conversions ----
    conv_hl<<<(MR * DM + 255) / 256, 256>>>(x, xh, xl, (long long)MR * DM);
    conv_hl<<<(DM * VDIM + 255) / 256, 256>>>(Wv, Wvh, Wvl, (long long)DM * VDIM);
    convT_hl<<<dim3(QKVN / 32, DM / 32, 1), tB>>>(Wqkv, WqkvTh, WqkvTl, DM, QKVN);
    convT_hl<<<dim3(DM / 32, VDIM / 32, 1), tB>>>(Wo, WoTh, WoTl, VDIM, DM);

    // ---- WvWo = Wv @ Wo (split-K over 8), then transpose-convert ----
    tgemm_nt<<<dim3(DM / 128, DM / 128, WSPLIT), 256, SMEM_DYN>>>(
        Wvh, Wvl, WoTh, WoTl, nullptr, WvWoP,
        VDIM / WSPLIT, VDIM, VDIM, DM,
        (long long)(VDIM / WSPLIT), (long long)(VDIM / WSPLIT), (long long)DM * DM, 1.0f);
    reduce_wvwo_kernel<<<(DM * DM + 255) / 256, 256>>>();
    convT_hl<<<dim3(DM / 32, DM / 32, 1), tB>>>(WvWo, WvWoTh, WvWoTl, DM, DM);
    bvwo_part_kernel<<<BSPLIT, DM>>>(bv, Wo);
    reduce_bvwo_kernel<<<1, DM>>>();

    // ---- QKV = x @ Wqkv + bqkv ----
    tgemm_nt<<<dim3(QKVN / 128, MR / 128, 1), 256, SMEM_DYN>>>(
        xh, xl, WqkvTh, WqkvTl, bqkv, QKV,
        DM, DM, DM, QKVN, 0, 0, 0, 1.0f);
    conv_hl<<<((long long)MR * QKVN + 255) / 256, 256>>>(QKV, QKVh, QKVl, (long long)MR * QKVN);

    // ---- VW = x @ WvWo + bvWo ----
    tgemm_nt<<<dim3(DM / 128, MR / 128, 1), 256, SMEM_DYN>>>(
        xh, xl, WvWoTh, WvWoTl, bvWo, VW,
        DM, DM, DM, DM, 0, 0, 0, 1.0f);
    convT_hl<<<dim3(DM / 32, SEQ / 32, BATCH), tB>>>(VW, VWTh, VWTl, SEQ, DM);

    lam_kernel<<<1, 64>>>(lq1, lk1, lq2, lk2);

    // ---- logits: L1 = Q1@K1^T * 0.125, L2 = Q2@K2^T * 0.125 ----
    tgemm_nt<<<dim3(SEQ / 128, SEQ / 128, BATCH), 256, SMEM_DYN>>>(
        QKVh + 0, QKVl + 0, QKVh + 512, QKVl + 512, nullptr, L1,
        256, QKVN, QKVN, SEQ, sQ, sQ, sL, 0.125f);
    tgemm_nt<<<dim3(SEQ / 128, SEQ / 128, BATCH), 256, SMEM_DYN>>>(
        QKVh + 256, QKVl + 256, QKVh + 768, QKVl + 768, nullptr, L2,
        256, QKVN, QKVN, SEQ, sQ, sQ, sL, 0.125f);

    // ---- diff_attn (bf16 hi/lo out) ----
    softmax_diff_kernel<<<BATCH * SEQ, 256>>>(L1, L2);

    // ---- out = diff @ VW + bo ----
    tgemm_nt<<<dim3(DM / 128, SEQ / 128, BATCH), 256, SMEM_DYN>>>(
        Dh, Dl, VWTh, VWTl, bo, out,
        SEQ, SEQ, SEQ, DM, sL, (long long)DM * SEQ, (long long)SEQ * DM, 1.0f);
}

// round 5
// speedup vs baseline: 2.6006x; 1.0039x over previous
#include <cuda_runtime.h>
#include <cuda_bf16.h>
#include <stdint.h>
#include <math.h>

#define SEQ    2048
#define BATCH  2
#define DM     512
#define QKVN   1024
#define VDIM   8192
#define MR     (BATCH*SEQ)    // 4096
#define WSPLIT 8              // split-K for Wv@Wo
#define BSPLIT 64             // split-K for bv@Wo

// ---------------- scratch (static device globals; no allocation) ----------------
__device__ __nv_bfloat16 g_xh[MR*DM],        g_xl[MR*DM];
__device__ __nv_bfloat16 g_Wvh[DM*VDIM],     g_Wvl[DM*VDIM];
__device__ __nv_bfloat16 g_WoTh[DM*VDIM],    g_WoTl[DM*VDIM];
__device__ __nv_bfloat16 g_WqkvTh[QKVN*DM],  g_WqkvTl[QKVN*DM];
__device__ __nv_bfloat16 g_WvWoTh[DM*DM],    g_WvWoTl[DM*DM];
__device__ __nv_bfloat16 g_QKVh[MR*QKVN],    g_QKVl[MR*QKVN];
__device__ __nv_bfloat16 g_VWTh[BATCH*DM*SEQ], g_VWTl[BATCH*DM*SEQ];
__device__ __nv_bfloat16 g_Dh[(size_t)BATCH*SEQ*SEQ], g_Dl[(size_t)BATCH*SEQ*SEQ];
__device__ float g_QKV[MR*QKVN];
__device__ float g_WvWoP[WSPLIT*DM*DM];
__device__ float g_WvWo[DM*DM];
__device__ float g_bvWoP[BSPLIT*DM];
__device__ float g_bvWo[DM];
__device__ float g_VW[MR*DM];
__device__ float g_L1[(size_t)BATCH*SEQ*SEQ];
__device__ float g_L2[(size_t)BATCH*SEQ*SEQ];
__device__ float g_lam;

// ---------------- PTX helpers (sm_100-safe: HMMA/LDSM/LDGSTS only) ----------------
__device__ __forceinline__ uint32_t s2u(const void* p) {
    uint32_t a;
    asm("{ .reg .u64 t; cvta.to.shared.u64 t, %1; cvt.u32.u64 %0, t; }" : "=r"(a) : "l"(p));
    return a;
}

#define CP16(dst, src) \
    asm volatile("cp.async.cg.shared.global [%0], [%1], 16;" :: "r"(dst), "l"(src))

__device__ __forceinline__ void ldm_x4(uint32_t* r, uint32_t addr) {
    asm volatile("ldmatrix.sync.aligned.m8n8.x4.shared.b16 {%0, %1, %2, %3}, [%4];"
                 : "=r"(r[0]), "=r"(r[1]), "=r"(r[2]), "=r"(r[3]) : "r"(addr));
}

__device__ __forceinline__ void mma16816(float* c, const uint32_t* a, const uint32_t* b) {
    asm volatile(
        "mma.sync.aligned.m16n8k16.row.col.f32.bf16.bf16.f32 "
        "{%0, %1, %2, %3}, {%4, %5, %6, %7}, {%8, %9}, {%0, %1, %2, %3};"
        : "+f"(c[0]), "+f"(c[1]), "+f"(c[2]), "+f"(c[3])
        : "r"(a[0]), "r"(a[1]), "r"(a[2]), "r"(a[3]), "r"(b[0]), "r"(b[1]));
}

// ---------------- HMMA NT GEMM (bf16 hi/lo split, fp32 accum) ----------------
// C[M,N] = alpha * A @ B^T (+ bias[col]).  A: [M,K] lda, B: [N,K] ldb, K-contiguous.
// 128x128 tile, BK=64, 2-stage cp.async double buffer, 8 warps (4m x 2n), warp 32x64.
// blockIdx.z advances by zA/zB/zC elements. Requires M%128==0, N%128==0, K%64==0.
#define TSTRIDE     144                 // smem row stride bytes (128 data + 16 pad)
#define MAT_BYTES   (128 * TSTRIDE)     // 18432
#define STAGE_BYTES (4 * MAT_BYTES)     // 73728 (Ah, Al, Bh, Bl)
#define SMEM_DYN    (2 * STAGE_BYTES)   // 147456

__global__ __launch_bounds__(256)
void tgemm_nt(const __nv_bfloat16* __restrict__ Ah, const __nv_bfloat16* __restrict__ Al,
              const __nv_bfloat16* __restrict__ Bh, const __nv_bfloat16* __restrict__ Bl,
              const float* __restrict__ bias, float* __restrict__ C,
              int K, int lda, int ldb, int ldc,
              long long zA, long long zB, long long zC, float alpha)
{
    extern __shared__ char dsm[];
    const uint32_t sbase = s2u(dsm);
    const int tid = threadIdx.x;
    const int lane = tid & 31;
    const int wid = tid >> 5;
    const long long z = blockIdx.z;
    Ah += z * zA;  Al += z * zA;
    Bh += z * zB;  Bl += z * zB;
    C  += z * zC;
    const int brow = blockIdx.y * 128;
    const int bcol = blockIdx.x * 128;
    const int wm0 = (wid & 3) * 32;      // warp m offset within tile
    const int wn0 = (wid >> 2) * 64;     // warp n offset within tile

    float acc[2][8][4];
    #pragma unroll
    for (int i = 0; i < 2; i++)
        #pragma unroll
        for (int j = 0; j < 8; j++)
            #pragma unroll
            for (int k = 0; k < 4; k++) acc[i][j][k] = 0.f;

    auto load_stage = [&](int s, int c) {
        const uint32_t sb = sbase + s * STAGE_BYTES;
        #pragma unroll
        for (int j = 0; j < 4; j++) {
            const int v = tid + j * 256;         // 0..1023
            const int row = v >> 3;              // 0..127
            const int c16 = v & 7;               // 16B block within 128B row
            const long long ga = (long long)(brow + row) * lda + c * 64 + c16 * 8;
            const long long gb = (long long)(bcol + row) * ldb + c * 64 + c16 * 8;
            const uint32_t so = row * TSTRIDE + c16 * 16;
            CP16(sb + so,                 Ah + ga);
            CP16(sb + MAT_BYTES + so,     Al + ga);
            CP16(sb + 2 * MAT_BYTES + so, Bh + gb);
            CP16(sb + 3 * MAT_BYTES + so, Bl + gb);
        }
    };

    auto compute_stage = [&](int s) {
        const uint32_t sb = sbase + s * STAGE_BYTES;
        const uint32_t aH = sb, aL = sb + MAT_BYTES;
        const uint32_t bH = sb + 2 * MAT_BYTES, bL = sb + 3 * MAT_BYTES;
        #pragma unroll
        for (int ks = 0; ks < 64; ks += 16) {
            uint32_t ah[2][4], al[2][4], bh[8][2], bl[8][2];
            #pragma unroll
            for (int mt = 0; mt < 2; mt++) {
                const int r  = wm0 + mt * 16 + (lane & 15);
                const int kk = ks + ((lane >> 4) & 1) * 8;
                const uint32_t off = r * TSTRIDE + kk * 2;
                ldm_x4(ah[mt], aH + off);
                ldm_x4(al[mt], aL + off);
            }
            #pragma unroll
            for (int nt = 0; nt < 4; nt++) {
                const int r  = wn0 + nt * 16 + (lane & 7) + ((lane >> 4) & 1) * 8;
                const int kk = ks + ((lane >> 3) & 1) * 8;
                const uint32_t off = r * TSTRIDE + kk * 2;
                uint32_t t0[4], t1[4];
                ldm_x4(t0, bH + off);
                ldm_x4(t1, bL + off);
                bh[2*nt][0] = t0[0]; bh[2*nt][1] = t0[1];
                bh[2*nt+1][0] = t0[2]; bh[2*nt+1][1] = t0[3];
                bl[2*nt][0] = t1[0]; bl[2*nt][1] = t1[1];
                bl[2*nt+1][0] = t1[2]; bl[2*nt+1][1] = t1[3];
            }
            // term 1: hi*hi
            #pragma unroll
            for (int mt = 0; mt < 2; mt++)
                #pragma unroll
                for (int n8 = 0; n8 < 8; n8++)
                    mma16816(acc[mt][n8], ah[mt], bh[n8]);
            // term 2: hi*lo
            #pragma unroll
            for (int mt = 0; mt < 2; mt++)
                #pragma unroll
                for (int n8 = 0; n8 < 8; n8++)
                    mma16816(acc[mt][n8], ah[mt], bl[n8]);
            // term 3: lo*hi
            #pragma unroll
            for (int mt = 0; mt < 2; mt++)
                #pragma unroll
                for (int n8 = 0; n8 < 8; n8++)
                    mma16816(acc[mt][n8], al[mt], bh[n8]);
        }
    };

    const int NC = K >> 6;

    load_stage(0, 0);
    asm volatile("cp.async.commit_group;" ::: "memory");

    for (int c = 0; c < NC; c++) {
        if (c + 1 < NC) {
            load_stage((c + 1) & 1, c + 1);
            asm volatile("cp.async.commit_group;" ::: "memory");
            asm volatile("cp.async.wait_group 1;" ::: "memory");
        } else {
            asm volatile("cp.async.wait_group 0;" ::: "memory");
        }
        __syncthreads();
        compute_stage(c & 1);
        __syncthreads();
    }

    // epilogue: mma C layout -> global
    #pragma unroll
    for (int mt = 0; mt < 2; mt++) {
        const int row0 = brow + wm0 + mt * 16 + (lane >> 2);
        #pragma unroll
        for (int n8 = 0; n8 < 8; n8++) {
            const int col = bcol + wn0 + n8 * 8 + (lane & 3) * 2;
            float b0 = 0.f, b1 = 0.f;
            if (bias) { b0 = bias[col]; b1 = bias[col + 1]; }
            float2 v0, v1;
            v0.x = acc[mt][n8][0] * alpha + b0;
            v0.y = acc[mt][n8][1] * alpha + b1;
            v1.x = acc[mt][n8][2] * alpha + b0;
            v1.y = acc[mt][n8][3] * alpha + b1;
            *(float2*)&C[(long long)row0 * ldc + col] = v0;
            *(float2*)&C[(long long)(row0 + 8) * ldc + col] = v1;
        }
    }
}

// ---------------- fp32 -> bf16 hi/lo converters ----------------
__global__ void conv_hl(const float* __restrict__ in, __nv_bfloat16* __restrict__ oh,
                        __nv_bfloat16* __restrict__ ol, long long n)
{
    long long i = (long long)blockIdx.x * blockDim.x + threadIdx.x;
    if (i < n) {
        float a = in[i];
        __nv_bfloat16 h = __float2bfloat16(a);
        oh[i] = h;
        ol[i] = __float2bfloat16(a - __bfloat162float(h));
    }
}

// in: fp32 [Z, R, C] -> out hi/lo: [Z, C, R]
__global__ void convT_hl(const float* __restrict__ in, __nv_bfloat16* __restrict__ oh,
                         __nv_bfloat16* __restrict__ ol, int R, int C)
{
    __shared__ float t[32][33];
    const long long zo = (long long)blockIdx.z * R * C;
    const int r0 = blockIdx.y * 32, c0 = blockIdx.x * 32;
    const int tx = threadIdx.x, ty = threadIdx.y;
    #pragma unroll
    for (int i = 0; i < 32; i += 8)
        t[ty + i][tx] = in[zo + (long long)(r0 + ty + i) * C + (c0 + tx)];
    __syncthreads();
    #pragma unroll
    for (int i = 0; i < 32; i += 8) {
        float a = t[tx][ty + i];
        __nv_bfloat16 h = __float2bfloat16(a);
        long long oi = zo + (long long)(c0 + ty + i) * R + (r0 + tx);
        oh[oi] = h;
        ol[oi] = __float2bfloat16(a - __bfloat162float(h));
    }
}

// ---------------- split-K reductions (deterministic) ----------------
__global__ void reduce_wvwo_kernel()
{
    int i = blockIdx.x * blockDim.x + threadIdx.x;
    if (i < DM * DM) {
        float s = 0.f;
        #pragma unroll
        for (int zz = 0; zz < WSPLIT; zz++) s += g_WvWoP[zz * DM * DM + i];
        g_WvWo[i] = s;
    }
}

__global__ void bvwo_part_kernel(const float* __restrict__ bv, const float* __restrict__ Wo)
{
    int n = threadIdx.x;
    int zz = blockIdx.x;
    float s = 0.f;
    int k0 = zz * (VDIM / BSPLIT);
    for (int k = k0; k < k0 + VDIM / BSPLIT; k++)
        s += bv[k] * Wo[(long long)k * DM + n];
    g_bvWoP[zz * DM + n] = s;
}

__global__ void reduce_bvwo_kernel()
{
    int n = threadIdx.x;
    float s = 0.f;
    #pragma unroll
    for (int zz = 0; zz < BSPLIT; zz++) s += g_bvWoP[zz * DM + n];
    g_bvWo[n] = s;
}

// ---------------- lambda scalar ----------------
__global__ void lam_kernel(const float* __restrict__ lq1, const float* __restrict__ lk1,
                           const float* __restrict__ lq2, const float* __restrict__ lk2)
{
    __shared__ float s1[64], s2[64];
    int t = threadIdx.x;
    s1[t] = lq1[t] * lk1[t];
    s2[t] = lq2[t] * lk2[t];
    __syncthreads();
    if (t == 0) {
        float a = 0.f, b = 0.f;
        for (int i = 0; i < 64; i++) { a += s1[i]; b += s2[i]; }
        g_lam = expf(a) - expf(b) + (0.8f - 0.6f * expf(-0.3f * 0.0f));
    }
}

// ---------------- fused dual softmax + diff; emits bf16 hi/lo ----------------
__global__ __launch_bounds__(256)
void softmax_diff_kernel(const float* __restrict__ L1, const float* __restrict__ L2)
{
    __shared__ float red[16];
    const long long bbase = (long long)blockIdx.x * SEQ;
    const int t = threadIdx.x;

    float v1[8], v2[8];
    #pragma unroll
    for (int i = 0; i < 8; i++) {
        v1[i] = L1[bbase + t + i * 256];
        v2[i] = L2[bbase + t + i * 256];
    }

    float m1 = -1e30f, m2 = -1e30f;
    #pragma unroll
    for (int i = 0; i < 8; i++) { m1 = fmaxf(m1, v1[i]); m2 = fmaxf(m2, v2[i]); }
    #pragma unroll
    for (int o = 16; o > 0; o >>= 1) {
        m1 = fmaxf(m1, __shfl_xor_sync(0xffffffffu, m1, o));
        m2 = fmaxf(m2, __shfl_xor_sync(0xffffffffu, m2, o));
    }
    const int w = t >> 5, l = t & 31;
    if (l == 0) { red[w] = m1; red[8 + w] = m2; }
    __syncthreads();
    float M1 = red[0], M2 = red[8];
    #pragma unroll
    for (int i = 1; i < 8; i++) { M1 = fmaxf(M1, red[i]); M2 = fmaxf(M2, red[8 + i]); }
    __syncthreads();

    float s1 = 0.f, s2 = 0.f;
    #pragma unroll
    for (int i = 0; i < 8; i++) {
        v1[i] = __expf(v1[i] - M1); s1 += v1[i];
        v2[i] = __expf(v2[i] - M2); s2 += v2[i];
    }
    #pragma unroll
    for (int o = 16; o > 0; o >>= 1) {
        s1 += __shfl_xor_sync(0xffffffffu, s1, o);
        s2 += __shfl_xor_sync(0xffffffffu, s2, o);
    }
    if (l == 0) { red[w] = s1; red[8 + w] = s2; }
    __syncthreads();
    float S1 = 0.f, S2 = 0.f;
    #pragma unroll
    for (int i = 0; i < 8; i++) { S1 += red[i]; S2 += red[8 + i]; }

    const float r1 = 1.f / S1;
    const float r2 = g_lam / S2;
    #pragma unroll
    for (int i = 0; i < 8; i++) {
        float d = v1[i] * r1 - v2[i] * r2;
        __nv_bfloat16 h = __float2bfloat16(d);
        long long idx = bbase + t + i * 256;
        g_Dh[idx] = h;
        g_Dl[idx] = __float2bfloat16(d - __bfloat162float(h));
    }
}

// ---------------- driver ----------------
extern "C" void kernel_launch(void* const* d_in, const int* in_sizes, int n_in,
                              void* d_out, int out_size)
{
    const float* x    = (const float*)d_in[0];
    const float* Wqkv = (const float*)d_in[1];
    const float* bqkv = (const float*)d_in[2];
    const float* Wv   = (const float*)d_in[3];
    const float* bv   = (const float*)d_in[4];
    const float* Wo   = (const float*)d_in[5];
    const float* bo   = (const float*)d_in[6];
    const float* lq1  = (const float*)d_in[7];
    const float* lk1  = (const float*)d_in[8];
    const float* lq2  = (const float*)d_in[9];
    const float* lk2  = (const float*)d_in[10];
    float* out = (float*)d_out;

    cudaFuncSetAttribute(tgemm_nt, cudaFuncAttributeMaxDynamicSharedMemorySize, SMEM_DYN);

    __nv_bfloat16 *xh, *xl, *Wvh, *Wvl, *WoTh, *WoTl, *WqkvTh, *WqkvTl;
    __nv_bfloat16 *WvWoTh, *WvWoTl, *QKVh, *QKVl, *VWTh, *VWTl, *Dh, *Dl;
    float *QKV, *WvWoP, *WvWo, *bvWo, *VW, *L1, *L2;
    cudaGetSymbolAddress((void**)&xh, g_xh);       cudaGetSymbolAddress((void**)&xl, g_xl);
    cudaGetSymbolAddress((void**)&Wvh, g_Wvh);     cudaGetSymbolAddress((void**)&Wvl, g_Wvl);
    cudaGetSymbolAddress((void**)&WoTh, g_WoTh);   cudaGetSymbolAddress((void**)&WoTl, g_WoTl);
    cudaGetSymbolAddress((void**)&WqkvTh, g_WqkvTh); cudaGetSymbolAddress((void**)&WqkvTl, g_WqkvTl);
    cudaGetSymbolAddress((void**)&WvWoTh, g_WvWoTh); cudaGetSymbolAddress((void**)&WvWoTl, g_WvWoTl);
    cudaGetSymbolAddress((void**)&QKVh, g_QKVh);   cudaGetSymbolAddress((void**)&QKVl, g_QKVl);
    cudaGetSymbolAddress((void**)&VWTh, g_VWTh);   cudaGetSymbolAddress((void**)&VWTl, g_VWTl);
    cudaGetSymbolAddress((void**)&Dh, g_Dh);       cudaGetSymbolAddress((void**)&Dl, g_Dl);
    cudaGetSymbolAddress((void**)&QKV, g_QKV);
    cudaGetSymbolAddress((void**)&WvWoP, g_WvWoP);
    cudaGetSymbolAddress((void**)&WvWo, g_WvWo);
    cudaGetSymbolAddress((void**)&bvWo, g_bvWo);
    cudaGetSymbolAddress((void**)&VW, g_VW);
    cudaGetSymbolAddress((void**)&L1, g_L1);
    cudaGetSymbolAddress((void**)&L2, g_L2);

    const long long sQ = (long long)SEQ * QKVN;
    const long long sL = (long long)SEQ * SEQ;
    const dim3 tB(32, 8);

    // ---- input conversions ----
    conv_hl<<<(MR * DM + 255) / 256, 256>>>(x, xh, xl, (long long)MR * DM);
    conv_hl<<<(DM * VDIM + 255) / 256, 256>>>(Wv, Wvh, Wvl, (long long)DM * VDIM);
    convT_hl<<<dim3(QKVN / 32, DM / 32, 1), tB>>>(Wqkv, WqkvTh, WqkvTl, DM, QKVN);
    convT_hl<<<dim3(DM / 32, VDIM / 32, 1), tB>>>(Wo, WoTh, WoTl, VDIM, DM);

    // ---- WvWo = Wv @ Wo (split-K over 8), then transpose-convert ----
    tgemm_nt<<<dim3(DM / 128, DM / 128, WSPLIT), 256, SMEM_DYN>>>(
        Wvh, Wvl, WoTh, WoTl, nullptr, WvWoP,
        VDIM / WSPLIT, VDIM, VDIM, DM,
        (long long)(VDIM / WSPLIT), (long long)(VDIM / WSPLIT), (long long)DM * DM, 1.0f);
    reduce_wvwo_kernel<<<(DM * DM + 255) / 256, 256>>>();
    convT_hl<<<dim3(DM / 32, DM / 32, 1), tB>>>(WvWo, WvWoTh, WvWoTl, DM, DM);
    bvwo_part_kernel<<<BSPLIT, DM>>>(bv, Wo);
    reduce_bvwo_kernel<<<1, DM>>>();

    // ---- QKV = x @ Wqkv + bqkv ----
    tgemm_nt<<<dim3(QKVN / 128, MR / 128, 1), 256, SMEM_DYN>>>(
        xh, xl, WqkvTh, WqkvTl, bqkv, QKV,
        DM, DM, DM, QKVN, 0, 0, 0, 1.0f);
    conv_hl<<<((long long)MR * QKVN + 255) / 256, 256>>>(QKV, QKVh, QKVl, (long long)MR * QKVN);

    // ---- VW = x @ WvWo + bvWo ----
    tgemm_nt<<<dim3(DM / 128, MR / 128, 1), 256, SMEM_DYN>>>(
        xh, xl, WvWoTh, WvWoTl, bvWo, VW,
        DM, DM, DM, DM, 0, 0, 0, 1.0f);
    convT_hl<<<dim3(DM / 32, SEQ / 32, BATCH), tB>>>(VW, VWTh, VWTl, SEQ, DM);

    lam_kernel<<<1, 64>>>(lq1, lk1, lq2, lk2);

    // ---- logits: L1 = Q1@K1^T * 0.125, L2 = Q2@K2^T * 0.125 ----
    tgemm_nt<<<dim3(SEQ / 128, SEQ / 128, BATCH), 256, SMEM_DYN>>>(
        QKVh + 0, QKVl + 0, QKVh + 512, QKVl + 512, nullptr, L1,
        256, QKVN, QKVN, SEQ, sQ, sQ, sL, 0.125f);
    tgemm_nt<<<dim3(SEQ / 128, SEQ / 128, BATCH), 256, SMEM_DYN>>>(
        QKVh + 256, QKVl + 256, QKVh + 768, QKVl + 768, nullptr, L2,
        256, QKVN, QKVN, SEQ, sQ, sQ, sL, 0.125f);

    // ---- diff_attn (bf16 hi/lo out) ----
    softmax_diff_kernel<<<BATCH * SEQ, 256>>>(L1, L2);

    // ---- out = diff @ VW + bo ----
    tgemm_nt<<<dim3(DM / 128, SEQ / 128, BATCH), 256, SMEM_DYN>>>(
        Dh, Dl, VWTh, VWTl, bo, out,
        SEQ, SEQ, SEQ, DM, sL, (long long)DM * SEQ, (long long)SEQ * DM, 1.0f);
}